// round 16
// baseline (speedup 1.0000x reference)
#include <cuda_runtime.h>
#include <cuda_fp16.h>
#include <mma.h>

using namespace nvcuda;

#define N_NODES 50000
#define N_EDGES 1600000
#define GEMM_GRID 444
#define N_TILES 3125          // 50000 / 16

typedef unsigned long long ull;

// Scratch (device globals — no allocation allowed)
__device__ __align__(16) __half g_h[(size_t)N_NODES * 128];  // projected fp16 [N,128]
__device__ int    g_rowptr[N_NODES + 1];                     // CSR offsets (dst sorted)
__device__ __align__(16) __half g_Wh[128 * 128];             // W fp16 row-major [k][c]

// ---------------------------------------------------------------------------
// Packed f32x2 helpers (packs/unpacks of distinct values are allocation-only)
// ---------------------------------------------------------------------------
__device__ __forceinline__ ull fma2(ull a, ull b, ull c) {
    ull d;
    asm("fma.rn.f32x2 %0, %1, %2, %3;" : "=l"(d) : "l"(a), "l"(b), "l"(c));
    return d;
}
__device__ __forceinline__ ull mul2(ull a, ull b) {
    ull d;
    asm("mul.rn.f32x2 %0, %1, %2;" : "=l"(d) : "l"(a), "l"(b));
    return d;
}
__device__ __forceinline__ ull dup2(float x) {
    ull r;
    asm("mov.b64 %0, {%1, %1};" : "=l"(r) : "f"(x));
    return r;
}
__device__ __forceinline__ float2 unpack2(ull u) {
    float2 f;
    asm("mov.b64 {%0, %1}, %2;" : "=f"(f.x), "=f"(f.y) : "l"(u));
    return f;
}
// half2 (as u32) -> packed f32x2 (2 F2F, pack free)
__device__ __forceinline__ ull h2f2(unsigned int h) {
    ull r;
    asm("{\n\t"
        ".reg .b16 lo, hi;\n\t"
        ".reg .f32 f0, f1;\n\t"
        "mov.b32 {lo, hi}, %1;\n\t"
        "cvt.f32.f16 f0, lo;\n\t"
        "cvt.f32.f16 f1, hi;\n\t"
        "mov.b64 %0, {f0, f1};\n\t"
        "}" : "=l"(r) : "r"(h));
    return r;
}
__device__ __forceinline__ unsigned int h2_as_u32(__half2 h) {
    union { __half2 h; unsigned int u; } cvt;
    cvt.h = h;
    return cvt.u;
}

// ---------------------------------------------------------------------------
// Kernel 0: W -> fp16 (one-time)
// ---------------------------------------------------------------------------
__global__ void wh_kernel(const float* __restrict__ W) {
    const int i = blockIdx.x * 256 + threadIdx.x;
    if (i < 128 * 128) g_Wh[i] = __float2half(__ldg(&W[i]));
}

// ---------------------------------------------------------------------------
// Kernel 1: h = feat @ W via wmma — persistent blocks, B-frags in registers.
// (R15 version, measured ~15-18us. Unchanged.)
// ---------------------------------------------------------------------------
__global__ void __launch_bounds__(256) gemm_kernel(const float* __restrict__ feat) {
    __shared__ __align__(16) __half sA[16 * 136];     // padded ldm=136
    __shared__ __align__(16) float sStage[8 * 256];

    const int tid = threadIdx.x;
    const int w = tid >> 5;
    const int l = tid & 31;

    wmma::fragment<wmma::matrix_b, 16, 16, 16, __half, wmma::row_major> B[8];
#pragma unroll
    for (int k = 0; k < 8; k++)
        wmma::load_matrix_sync(B[k], g_Wh + k * 16 * 128 + w * 16, 128);

    for (int t = blockIdx.x; t < N_TILES; t += GEMM_GRID) {
        const int base = t * 16;

        __syncthreads();
        for (int i = tid; i < 512; i += 256) {
            const int r = i >> 5, c4 = i & 31;
            const float4 f = __ldg((const float4*)(feat + (size_t)(base + r) * 128) + c4);
            unsigned int* dp = (unsigned int*)sA + r * 68 + c4 * 2;
            dp[0] = h2_as_u32(__floats2half2_rn(f.x, f.y));
            dp[1] = h2_as_u32(__floats2half2_rn(f.z, f.w));
        }
        __syncthreads();

        wmma::fragment<wmma::accumulator, 16, 16, 16, float> c;
        wmma::fill_fragment(c, 0.0f);
#pragma unroll
        for (int k = 0; k < 8; k++) {
            wmma::fragment<wmma::matrix_a, 16, 16, 16, __half, wmma::row_major> a;
            wmma::load_matrix_sync(a, sA + k * 16, 136);
            wmma::mma_sync(c, a, B[k], c);
        }

        wmma::store_matrix_sync(sStage + w * 256, c, 16, wmma::mem_row_major);
        __syncwarp();
        {
            const int r = l >> 1, c0 = (l & 1) * 8;
            const float* sp = sStage + w * 256 + r * 16 + c0;
            uint4 o;
            o.x = h2_as_u32(__floats2half2_rn(sp[0], sp[1]));
            o.y = h2_as_u32(__floats2half2_rn(sp[2], sp[3]));
            o.z = h2_as_u32(__floats2half2_rn(sp[4], sp[5]));
            o.w = h2_as_u32(__floats2half2_rn(sp[6], sp[7]));
            *(uint4*)(g_h + (size_t)(base + r) * 128 + w * 16 + c0) = o;
        }
        __syncwarp();
    }
}

// ---------------------------------------------------------------------------
// Kernel 2: CSR offsets via binary search (dst is sorted).
// ---------------------------------------------------------------------------
__global__ void rowptr_kernel(const int* __restrict__ dst) {
    const int n = blockIdx.x * blockDim.x + threadIdx.x;
    if (n > N_NODES) return;
    int lo = 0, hi = N_EDGES;
    while (lo < hi) {
        const int mid = (lo + hi) >> 1;
        if (__ldg(&dst[mid]) < n) lo = mid + 1;
        else hi = mid;
    }
    g_rowptr[n] = lo;
}

// ---------------------------------------------------------------------------
// Kernel 3: fused scores + softmax + aggregation. R11 SHAPE (one warp/node,
// uint2/lane gather, 4-edge buffer, 8 lanes/head — the shape that measured
// occ=84%, issue=76.5%) with in-place issue cuts:
//  * f32x2 dot (mul2+fma2) and acc (2 fma2) on the already-packed F2F output
//  * src read as one int4 per 4 edges (alignment prolog/tail)
// ~19 effective issues/edge vs ~26 before.
// ---------------------------------------------------------------------------
__global__ void __launch_bounds__(64) attn_kernel(const int* __restrict__ src,
                                                  float* __restrict__ out) {
    const int n = (int)((blockIdx.x * 64 + threadIdx.x) >> 5);
    const int l = threadIdx.x & 31;
    if (n >= N_NODES) return;

    const int beg = g_rowptr[n];
    const int end = g_rowptr[n + 1];

    const uint2* __restrict__ H2 = (const uint2*)g_h;

    // 1/sqrt(32) * log2(e)
    const float scale_d = 0.17677669529663689f * 1.4426950408889634f;
    ull hd0, hd1;
    {
        const uint2 v = H2[(size_t)n * 32 + l];
        const ull sc2 = dup2(scale_d);
        hd0 = mul2(h2f2(v.x), sc2);
        hd1 = mul2(h2f2(v.y), sc2);
    }

    ull acc0 = 0ull, acc1 = 0ull;
    float s = 0.f;

    // ---- per-edge body (f32x2 math) ----
#define ATTN_EDGE(vx, vy)                                            \
    {                                                                \
        const ull a0 = h2f2(vx);                                     \
        const ull a1 = h2f2(vy);                                     \
        const ull d2 = fma2(a1, hd1, mul2(a0, hd0));                 \
        const float2 dd = unpack2(d2);                               \
        float d = dd.x + dd.y;                                       \
        d += __shfl_xor_sync(0xffffffffu, d, 1);                     \
        d += __shfl_xor_sync(0xffffffffu, d, 2);                     \
        d += __shfl_xor_sync(0xffffffffu, d, 4);                     \
        const float p = exp2f(d);                                    \
        s += p;                                                      \
        const ull p2 = dup2(p);                                      \
        acc0 = fma2(p2, a0, acc0);                                   \
        acc1 = fma2(p2, a1, acc1);                                   \
    }

    int e = beg;
    const int e_al = min(end, (beg + 3) & ~3);          // align to int4
    for (; e < e_al; e++) {
        const int sn = __ldg(&src[e]);
        const uint2 v = __ldg(&H2[(size_t)sn * 32 + l]);
        ATTN_EDGE(v.x, v.y);
    }
    const int e_main = e_al + ((end - e_al) & ~3);
    for (; e < e_main; e += 4) {
        const int4 sn4 = __ldg((const int4*)(src + e));  // 1 LDG per 4 edges
        uint2 v[4];
        v[0] = __ldg(&H2[(size_t)sn4.x * 32 + l]);
        v[1] = __ldg(&H2[(size_t)sn4.y * 32 + l]);
        v[2] = __ldg(&H2[(size_t)sn4.z * 32 + l]);
        v[3] = __ldg(&H2[(size_t)sn4.w * 32 + l]);
#pragma unroll
        for (int j = 0; j < 4; j++) ATTN_EDGE(v[j].x, v[j].y);
    }
    for (; e < end; e++) {
        const int sn = __ldg(&src[e]);
        const uint2 v = __ldg(&H2[(size_t)sn * 32 + l]);
        ATTN_EDGE(v.x, v.y);
    }
#undef ATTN_EDGE

    const float inv = (s > 0.f) ? (1.0f / s) : 0.f;
    const float2 x0 = unpack2(acc0);
    const float2 x1 = unpack2(acc1);
    float4 o;
    o.x = x0.x * inv; o.y = x0.y * inv;
    o.z = x1.x * inv; o.w = x1.y * inv;
    ((float4*)out)[(size_t)n * 32 + l] = o;
}

// ---------------------------------------------------------------------------
extern "C" void kernel_launch(void* const* d_in, const int* in_sizes, int n_in,
                              void* d_out, int out_size) {
    const float* feat = (const float*)d_in[0];   // [N, 128] f32
    const int*   src  = (const int*)d_in[1];     // [E] i32
    const int*   dst  = (const int*)d_in[2];     // [E] i32, sorted
    const float* W    = (const float*)d_in[3];   // [128, 128] f32
    float* out = (float*)d_out;                  // [N, 128] f32

    wh_kernel<<<64, 256>>>(W);
    rowptr_kernel<<<(N_NODES + 1 + 255) / 256, 256>>>(dst);
    gemm_kernel<<<GEMM_GRID, 256>>>(feat);
    attn_kernel<<<(N_NODES * 32 + 63) / 64, 64>>>(src, out);
}